// round 15
// baseline (speedup 1.0000x reference)
#include <cuda_runtime.h>
#include <cstdint>
#include <math.h>

#define D_    1024
#define DL_   1024
#define DH_   2048
#define NL_   64
#define H_    16
#define E_    8
#define B_    2
#define T_    2048
#define NTOK  (B_*T_)
#define HALF_ 32
#define SLOTS (NTOK*2)
#define SLOTP (SLOTS + E_*128)   /* padded slots: 9216 */
#define PT    (SLOTP/128)        /* 72 tiles */

__device__ float g_Lq[NL_*DL_];
__device__ float g_K [NTOK*DL_];
__device__ float g_V [NTOK*DL_];
__device__ float g_Qx[NTOK*DL_];
__device__ float g_z [B_*NL_*DL_];
__device__ float g_Ql[B_*NL_*DL_];
__device__ float g_Kl[B_*NL_*DL_];
__device__ float g_Vl[B_*NL_*DL_];
__device__ float g_z2[B_*NL_*DL_];
__device__ float g_Kz[B_*NL_*DL_];
__device__ float g_Vz[B_*NL_*DL_];
__device__ float g_xl[NTOK*DL_];
__device__ float g_attnout[NTOK*D_];
__device__ float g_x1[NTOK*D_];
__device__ float g_moe[NTOK*D_];
__device__ float g_x2[NTOK*D_];
__device__ float g_lin[NTOK*D_];
__device__ float g_h [(size_t)SLOTP*DH_];
__device__ float g_xr[NTOK*D_];
__device__ int   g_counts[E_];
__device__ int   g_offsets[E_];
__device__ int   g_cursor[E_];
__device__ int   g_tile_expert[PT];
__device__ int   g_slot_token[SLOTP];
__device__ float g_slot_gate[SLOTP];
__device__ int   g_topi[NTOK*2];
__device__ float g_gate[NTOK*2];

// ----------------------------- tf32 helpers ----------------------------------
__device__ __forceinline__ uint32_t f2tf(float f) {
    uint32_t u; asm("cvt.rna.tf32.f32 %0, %1;" : "=r"(u) : "f"(f)); return u;
}
__device__ __forceinline__ float roundtf(float f) { return __uint_as_float(f2tf(f)); }
__device__ __forceinline__ uint32_t f2tf_bits(uint32_t b) {
    uint32_t u; asm("cvt.rna.tf32.f32 %0, %1;" : "=r"(u) : "f"(__uint_as_float(b))); return u;
}
__device__ __forceinline__ void mma_tf32(float* d, const uint32_t* a, const uint32_t* b) {
    asm volatile("mma.sync.aligned.m16n8k8.row.col.f32.tf32.tf32.f32 "
        "{%0,%1,%2,%3}, {%4,%5,%6,%7}, {%8,%9}, {%0,%1,%2,%3};\n"
        : "+f"(d[0]), "+f"(d[1]), "+f"(d[2]), "+f"(d[3])
        : "r"(a[0]), "r"(a[1]), "r"(a[2]), "r"(a[3]), "r"(b[0]), "r"(b[1]));
}
__device__ __forceinline__ void ldmatrix4(uint32_t* r, uint32_t addr) {
    asm volatile("ldmatrix.sync.aligned.m8n8.x4.shared.b16 {%0,%1,%2,%3}, [%4];"
        : "=r"(r[0]), "=r"(r[1]), "=r"(r[2]), "=r"(r[3]) : "r"(addr));
}
__device__ __forceinline__ void cpasync16(uint32_t dst, const void* src) {
    asm volatile("cp.async.cg.shared.global [%0], [%1], 16;\n" :: "r"(dst), "l"(src));
}
__device__ __forceinline__ void cpcommit() { asm volatile("cp.async.commit_group;\n" ::: "memory"); }
__device__ __forceinline__ void cpwait1()  { asm volatile("cp.async.wait_group 1;\n" ::: "memory"); }
__device__ __forceinline__ void cpwait2()  { asm volatile("cp.async.wait_group 2;\n" ::: "memory"); }

#define ASTR 36

// ----------------------------- rounding prep ----------------------------------
__global__ void round_kernel(const float4* __restrict__ s, float4* __restrict__ d, int n4) {
    int i = blockIdx.x * blockDim.x + threadIdx.x;
    if (i >= n4) return;
    float4 v = s[i];
    v.x = roundtf(v.x); v.y = roundtf(v.y); v.z = roundtf(v.z); v.w = roundtf(v.w);
    d[i] = v;
}

// ----------------------- 2-CTA/SM tf32 GEMM (BM128 x BN128) -------------------
#define BM 128
#define GBN 128
#define BK 32
#define GBSTR 136
#define GAW (BM*ASTR)
#define GBW (BK*GBSTR)
#define GSTG (GAW+GBW)
#define GSTAGES 2
#define SMEM_TG (GSTAGES*GSTG*4)

// expertMode: padded-tile map (grid.x over PT tiles); e = g_tile_expert[x].
// gatherA: A row = g_slot_token[slot]; scatterC: C[token] += gate*acc (atomic).
template<int CVTA>
__global__ void __launch_bounds__(256, 2) tgemm_kernel(
    const float* __restrict__ A, const float* __restrict__ Bm, float* __restrict__ C,
    int M, int N, int K, int expertMode, int gatherA, int scatterC, int splitK)
{
    extern __shared__ float dsm[];
    __shared__ int   rIn[BM];
    __shared__ int   rOut[BM];
    __shared__ float rGate[BM];

    const int tid = threadIdx.x;
    int kOff = 0, Kloc = K;
    int end;
    if (expertMode) {
        int e = g_tile_expert[blockIdx.x];
        if (e < 0) return;
        Bm += (size_t)e * K * N;
        end = g_offsets[e] + g_counts[e];
    } else {
        if (splitK > 1) { Kloc = K / splitK; kOff = blockIdx.z * Kloc; }
        if (blockIdx.x * BM >= M) return;
        end = M;
    }
    const int tile_m = blockIdx.x * BM;
    const int tile_n = blockIdx.y * GBN;

    if (tid < BM) {
        int m = tile_m + tid;
        if (m < end) {
            rIn[tid]   = gatherA  ? g_slot_token[m] : m;
            rOut[tid]  = scatterC ? g_slot_token[m] : m;
            rGate[tid] = scatterC ? g_slot_gate[m] : 1.f;
        } else { rIn[tid] = 0; rOut[tid] = -1; rGate[tid] = 0.f; }
    }
    __syncthreads();

    const uint32_t smem_u32 = (uint32_t)__cvta_generic_to_shared(dsm);
    const int lane = tid & 31;
    const int wid  = tid >> 5;
    const int wm = (wid >> 2) * 64;
    const int wn = (wid & 3) * 32;
    const int gid = lane >> 2, tig = lane & 3;
    const int lj = lane >> 3, lr = lane & 7;
    const uint32_t aLanePart = ((uint32_t)(wm + (lj & 1) * 8 + lr) * ASTR + (lj >> 1) * 4) * 4u;

    const int a_row = tid >> 3;
    const int a_kc  = (tid & 7) * 4;
    const int b_row = tid >> 5;
    const int b_nc  = (tid & 31) * 4;

    const int nkt = Kloc / BK;

    auto issue = [&](int kt) {
        const int s = kt & 1;
        const int k0 = kOff + kt * BK;
        const uint32_t aBase = smem_u32 + s * (GSTG * 4);
        const uint32_t bBase = aBase + GAW * 4;
        #pragma unroll
        for (int i = 0; i < 4; i++) {
            int row = a_row + i * 32;
            int ar = rIn[row];
            cpasync16(aBase + ((uint32_t)row * ASTR + a_kc) * 4u,
                      A + (size_t)ar * K + k0 + a_kc);
        }
        #pragma unroll
        for (int i = 0; i < 4; i++) {
            int row = b_row + i * 8;
            cpasync16(bBase + ((uint32_t)row * GBSTR + b_nc) * 4u,
                      Bm + (size_t)(k0 + row) * N + tile_n + b_nc);
        }
    };

    float acc[4][4][4];
    #pragma unroll
    for (int i = 0; i < 4; i++)
        #pragma unroll
        for (int j = 0; j < 4; j++)
            #pragma unroll
            for (int q = 0; q < 4; q++) acc[i][j][q] = 0.f;

    issue(0); cpcommit();
    if (nkt > 1) { issue(1); cpcommit(); }

    for (int kt = 0; kt < nkt; kt++) {
        cpwait1();
        __syncthreads();

        const int s = kt & 1;
        const uint32_t aBase = smem_u32 + s * (GSTG * 4) + aLanePart;
        const float* Bs = dsm + s * GSTG + GAW;

        #pragma unroll
        for (int ks = 0; ks < 4; ks++) {
            uint32_t af[4][4];
            #pragma unroll
            for (int mi = 0; mi < 4; mi++) {
                ldmatrix4(af[mi], aBase + mi * (16 * ASTR * 4) + ks * 32);
                if (CVTA) {
                    #pragma unroll
                    for (int q = 0; q < 4; q++) af[mi][q] = f2tf_bits(af[mi][q]);
                }
            }
            uint32_t bf[4][2];
            #pragma unroll
            for (int ni = 0; ni < 4; ni++) {
                int idx = (ks * 8 + tig) * GBSTR + wn + ni * 8 + gid;
                bf[ni][0] = f2tf(Bs[idx]);
                bf[ni][1] = f2tf(Bs[idx + 4 * GBSTR]);
            }
            #pragma unroll
            for (int mi = 0; mi < 4; mi++)
                #pragma unroll
                for (int ni = 0; ni < 4; ni++)
                    mma_tf32(acc[mi][ni], af[mi], bf[ni]);
        }
        __syncthreads();
        if (kt + 2 < nkt) issue(kt + 2);
        cpcommit();
    }

    const bool atom = (scatterC != 0) || (splitK > 1);
    #pragma unroll
    for (int mi = 0; mi < 4; mi++) {
        int rl0 = wm + mi * 16 + gid;
        int rl1 = rl0 + 8;
        int o0 = rOut[rl0], o1 = rOut[rl1];
        float g0 = rGate[rl0], g1 = rGate[rl1];
        #pragma unroll
        for (int ni = 0; ni < 4; ni++) {
            int c = tile_n + wn + ni * 8 + tig * 2;
            if (atom) {
                if (o0 >= 0) {
                    atomicAdd(&C[(size_t)o0 * N + c],     g0 * acc[mi][ni][0]);
                    atomicAdd(&C[(size_t)o0 * N + c + 1], g0 * acc[mi][ni][1]);
                }
                if (o1 >= 0) {
                    atomicAdd(&C[(size_t)o1 * N + c],     g1 * acc[mi][ni][2]);
                    atomicAdd(&C[(size_t)o1 * N + c + 1], g1 * acc[mi][ni][3]);
                }
            } else {
                if (o0 >= 0) *(float2*)&C[(size_t)o0 * N + c] = make_float2(acc[mi][ni][0], acc[mi][ni][1]);
                if (o1 >= 0) *(float2*)&C[(size_t)o1 * N + c] = make_float2(acc[mi][ni][2], acc[mi][ni][3]);
            }
        }
    }
}

// --------- fused MoE gemm1 + SwiGLU: 512 thr, 16 warps, 64x16 dual tile -------
#define FBN 128
#define FBSTR 136
#define FAW (BM*ASTR)
#define FBW (BK*FBSTR)
#define FSTAGE (FAW+2*FBW)
#define FSTAGES 3
#define SMEM_F (FSTAGES*FSTAGE*4)
__global__ void __launch_bounds__(512) moe_g1_kernel(
    const float* __restrict__ A, const float* __restrict__ Ww, const float* __restrict__ Wv)
{
    extern __shared__ float dsm[];
    __shared__ int rIn[BM];
    __shared__ int rOut[BM];

    const int tid = threadIdx.x;
    const int e = g_tile_expert[blockIdx.x];
    if (e < 0) return;
    const int end = g_offsets[e] + g_counts[e];
    const int tile_m = blockIdx.x * BM;
    const int tile_n = blockIdx.y * FBN;
    Ww += (size_t)e * D_ * DH_;
    Wv += (size_t)e * D_ * DH_;

    if (tid < BM) {
        int m = tile_m + tid;
        if (m < end) { rIn[tid] = g_slot_token[m]; rOut[tid] = m; }
        else         { rIn[tid] = 0; rOut[tid] = -1; }
    }
    __syncthreads();

    const uint32_t smem_u32 = (uint32_t)__cvta_generic_to_shared(dsm);
    const int lane = tid & 31;
    const int wid  = tid >> 5;                 // 0..15
    const int wm = (wid >> 3) * 64;            // 2 m-groups
    const int wn = (wid & 7) * 16;             // 8 n-groups
    const int gid = lane >> 2, tig = lane & 3;
    const int lj = lane >> 3, lr = lane & 7;
    const uint32_t aLanePart = ((uint32_t)(wm + (lj & 1) * 8 + lr) * ASTR + (lj >> 1) * 4) * 4u;

    // staging for 512 threads: A 128x32 (4 thr/row, 8 floats), B 32x128 each (16 thr/row, 8 floats)
    const int a_row = tid >> 2;
    const int a_kc  = (tid & 3) * 8;
    const int b_row = tid >> 4;
    const int b_nc  = (tid & 15) * 8;

    const int nkt = D_ / BK;

    auto issue = [&](int kt) {
        const int s = kt % FSTAGES;
        const int k0 = kt * BK;
        const uint32_t aBase = smem_u32 + s * (FSTAGE * 4);
        const uint32_t wBase = aBase + FAW * 4;
        const uint32_t vBase = wBase + FBW * 4;
        {
            int ar = rIn[a_row];
            const float* src = A + (size_t)ar * D_ + k0 + a_kc;
            uint32_t dst = aBase + ((uint32_t)a_row * ASTR + a_kc) * 4u;
            cpasync16(dst, src);
            cpasync16(dst + 16, src + 4);
        }
        {
            const float* ws = Ww + (size_t)(k0 + b_row) * DH_ + tile_n + b_nc;
            const float* vs = Wv + (size_t)(k0 + b_row) * DH_ + tile_n + b_nc;
            uint32_t wdst = wBase + ((uint32_t)b_row * FBSTR + b_nc) * 4u;
            uint32_t vdst = vBase + ((uint32_t)b_row * FBSTR + b_nc) * 4u;
            cpasync16(wdst, ws);       cpasync16(wdst + 16, ws + 4);
            cpasync16(vdst, vs);       cpasync16(vdst + 16, vs + 4);
        }
    };

    float accW[4][2][4], accV[4][2][4];
    #pragma unroll
    for (int i = 0; i < 4; i++)
        #pragma unroll
        for (int j = 0; j < 2; j++)
            #pragma unroll
            for (int q = 0; q < 4; q++) { accW[i][j][q] = 0.f; accV[i][j][q] = 0.f; }

    issue(0); cpcommit();
    if (nkt > 1) issue(1); cpcommit();

    for (int kt = 0; kt < nkt; kt++) {
        if (kt + 2 < nkt) issue(kt + 2);
        cpcommit();
        cpwait2();
        __syncthreads();

        const int s = kt % FSTAGES;
        const uint32_t aBase = smem_u32 + s * (FSTAGE * 4) + aLanePart;
        const float* Bw = dsm + s * FSTAGE + FAW;
        const float* Bv = Bw + FBW;

        #pragma unroll
        for (int ks = 0; ks < 4; ks++) {
            uint32_t af[4][4];
            #pragma unroll
            for (int mi = 0; mi < 4; mi++)
                ldmatrix4(af[mi], aBase + mi * (16 * ASTR * 4) + ks * 32);  // A pre-rounded
            uint32_t bw[2][2], bv[2][2];
            #pragma unroll
            for (int ni = 0; ni < 2; ni++) {
                int idx = (ks * 8 + tig) * FBSTR + wn + ni * 8 + gid;
                bw[ni][0] = f2tf(Bw[idx]);
                bw[ni][1] = f2tf(Bw[idx + 4 * FBSTR]);
                bv[ni][0] = f2tf(Bv[idx]);
                bv[ni][1] = f2tf(Bv[idx + 4 * FBSTR]);
            }
            #pragma unroll
            for (int mi = 0; mi < 4; mi++)
                #pragma unroll
                for (int ni = 0; ni < 2; ni++) {
                    mma_tf32(accW[mi][ni], af[mi], bw[ni]);
                    mma_tf32(accV[mi][ni], af[mi], bv[ni]);
                }
        }
        __syncthreads();
    }

    // epilogue: h = round(a * silu(b))
    #pragma unroll
    for (int mi = 0; mi < 4; mi++) {
        int rl0 = wm + mi * 16 + gid;
        int rl1 = rl0 + 8;
        int s0 = rOut[rl0], s1 = rOut[rl1];
        #pragma unroll
        for (int ni = 0; ni < 2; ni++) {
            int c = tile_n + wn + ni * 8 + tig * 2;
            if (s0 >= 0) {
                float b0 = accV[mi][ni][0], b1 = accV[mi][ni][1];
                float h0 = accW[mi][ni][0] * b0 / (1.f + __expf(-b0));
                float h1 = accW[mi][ni][1] * b1 / (1.f + __expf(-b1));
                *(float2*)&g_h[(size_t)s0 * DH_ + c] = make_float2(roundtf(h0), roundtf(h1));
            }
            if (s1 >= 0) {
                float b2 = accV[mi][ni][2], b3 = accV[mi][ni][3];
                float h2 = accW[mi][ni][2] * b2 / (1.f + __expf(-b2));
                float h3 = accW[mi][ni][3] * b3 / (1.f + __expf(-b3));
                *(float2*)&g_h[(size_t)s1 * DH_ + c] = make_float2(roundtf(h2), roundtf(h3));
            }
        }
    }
}

// ----------------------------- tiled attention (verbatim R14) -----------------
#define APAD 68
#define ATTN_SMEM (3*64*APAD*4)
__global__ void __launch_bounds__(256) attn_tile_kernel(
    const float* __restrict__ Q, int qbs,
    const float* __restrict__ Ksrc, const float* __restrict__ Vsrc, int kbs,
    float* __restrict__ Out, int obs, int causal)
{
    extern __shared__ float sm[];
    float* Ks = sm;
    float* Vs = sm + 64 * APAD;
    float* Ws = sm + 2 * 64 * APAD;

    const int tid = threadIdx.x;
    const int h = blockIdx.y, b = blockIdx.z;
    const int qtile = blockIdx.x * 64;

    {
        int row = tid >> 2;
        int c0 = (tid & 3) * 16;
        const float* kp = Ksrc + ((size_t)(b * kbs + row)) * DL_ + h * 64 + c0;
        const float* vp = Vsrc + ((size_t)(b * kbs + row)) * DL_ + h * 64 + c0;
        const float* qp = Q    + ((size_t)(b * qbs + qtile + row)) * DL_ + h * 64 + c0;
        #pragma unroll
        for (int j = 0; j < 4; j++) {
            *(float4*)&Ks[row * APAD + c0 + 4*j] = __ldg((const float4*)kp + j);
            *(float4*)&Vs[row * APAD + c0 + 4*j] = __ldg((const float4*)vp + j);
            *(float4*)&Ws[row * APAD + c0 + 4*j] = __ldg((const float4*)qp + j);
        }
    }
    __syncthreads();

    const int ty = tid >> 4, tx = tid & 15;
    const int q0 = ty * 4, j0 = tx * 4;

    float acc[4][4] = {};
    #pragma unroll
    for (int d4 = 0; d4 < 16; d4++) {
        float4 k4[4];
        #pragma unroll
        for (int kk = 0; kk < 4; kk++) k4[kk] = *(float4*)&Ks[(j0 + kk) * APAD + d4 * 4];
        #pragma unroll
        for (int i = 0; i < 4; i++) {
            float4 q4 = *(float4*)&Ws[(q0 + i) * APAD + d4 * 4];
            #pragma unroll
            for (int kk = 0; kk < 4; kk++)
                acc[i][kk] += q4.x * k4[kk].x + q4.y * k4[kk].y + q4.z * k4[kk].z + q4.w * k4[kk].w;
        }
    }
    #pragma unroll
    for (int i = 0; i < 4; i++)
        #pragma unroll
        for (int kk = 0; kk < 4; kk++) {
            float s = acc[i][kk] * 0.125f;
            if (causal && (j0 + kk > qtile + q0 + i)) s = -1e30f;
            acc[i][kk] = s;
        }
    __syncthreads();

    #pragma unroll
    for (int i = 0; i < 4; i++) {
        float m = fmaxf(fmaxf(acc[i][0], acc[i][1]), fmaxf(acc[i][2], acc[i][3]));
        #pragma unroll
        for (int off = 1; off < 16; off <<= 1) m = fmaxf(m, __shfl_xor_sync(0xffffffffu, m, off));
        float e[4], sum = 0.f;
        #pragma unroll
        for (int kk = 0; kk < 4; kk++) { e[kk] = __expf(acc[i][kk] - m); sum += e[kk]; }
        #pragma unroll
        for (int off = 1; off < 16; off <<= 1) sum += __shfl_xor_sync(0xffffffffu, sum, off);
        float inv = 1.f / sum;
        #pragma unroll
        for (int kk = 0; kk < 4; kk++) Ws[(q0 + i) * APAD + j0 + kk] = e[kk] * inv;
    }
    __syncthreads();

    float o[4][4] = {};
    const int d0 = tx * 4;
    for (int j = 0; j < 64; j++) {
        float4 v4 = *(float4*)&Vs[j * APAD + d0];
        #pragma unroll
        for (int i = 0; i < 4; i++) {
            float w = Ws[(q0 + i) * APAD + j];
            o[i][0] += w * v4.x; o[i][1] += w * v4.y;
            o[i][2] += w * v4.z; o[i][3] += w * v4.w;
        }
    }
    #pragma unroll
    for (int i = 0; i < 4; i++) {
        float4 r = make_float4(roundtf(o[i][0]), roundtf(o[i][1]),
                               roundtf(o[i][2]), roundtf(o[i][3]));
        *(float4*)&Out[((size_t)(b * obs + qtile + q0 + i)) * DL_ + h * 64 + d0] = r;
    }
}

// ----------------------------- RoPE ------------------------------------------
__global__ void rope_kernel(float* __restrict__ buf, const float* __restrict__ cosb,
                            const float* __restrict__ sinb) {
    int idx = blockIdx.x * blockDim.x + threadIdx.x;
    if (idx >= NTOK * H_ * HALF_) return;
    int j = idx & 31;
    int h = (idx >> 5) & 15;
    int r = idx >> 9;
    int t = r % T_;
    float c = cosb[t * HALF_ + j];
    float s = sinb[t * HALF_ + j];
    size_t base = (size_t)r * DL_ + h * 64 + 2 * j;
    float x1 = buf[base], x2 = buf[base + 1];
    buf[base]     = x1 * c - x2 * s;
    buf[base + 1] = x1 * s + x2 * c;
}

// ----------------------------- LayerNorm(+residual+bias), dual output --------
__global__ void add_ln_kernel(const float* __restrict__ src, const float* __restrict__ addv,
                              const float* __restrict__ g, const float* __restrict__ bt,
                              const float* __restrict__ bias, float* __restrict__ out,
                              float* __restrict__ out_r) {
    int row = blockIdx.x;
    int tid = threadIdx.x;
    const float* x = src + (size_t)row * D_;
    float v[4];
    #pragma unroll
    for (int i = 0; i < 4; i++) v[i] = x[tid + i * 256];
    __shared__ float red[256];
    float s = v[0] + v[1] + v[2] + v[3];
    red[tid] = s; __syncthreads();
    for (int o = 128; o > 0; o >>= 1) { if (tid < o) red[tid] += red[tid + o]; __syncthreads(); }
    float mean = red[0] * (1.f / 1024.f);
    __syncthreads();
    float d0 = v[0]-mean, d1 = v[1]-mean, d2 = v[2]-mean, d3 = v[3]-mean;
    red[tid] = d0*d0 + d1*d1 + d2*d2 + d3*d3; __syncthreads();
    for (int o = 128; o > 0; o >>= 1) { if (tid < o) red[tid] += red[tid + o]; __syncthreads(); }
    float stdv = sqrtf(red[0] * (1.f / 1023.f));
    float inv = 1.f / (stdv + 1e-6f);
    #pragma unroll
    for (int i = 0; i < 4; i++) {
        int c = tid + i * 256;
        float r = g[c] * (v[i] - mean) * inv + bt[c] + addv[(size_t)row * D_ + c];
        if (bias) r += bias[c];
        out[(size_t)row * D_ + c] = r;
        if (out_r) out_r[(size_t)row * D_ + c] = roundtf(r);
    }
}

// ----------------------------- router + routing ------------------------------
__global__ void router_kernel(const float* __restrict__ X, const float* __restrict__ Wr,
                              const float* __restrict__ br) {
    int n = blockIdx.x;
    int tid = threadIdx.x;
    int wrp = tid >> 5, lane = tid & 31;
    const float* xr = X + (size_t)n * D_;
    float p = 0.f;
    for (int d = lane; d < D_; d += 32) p += xr[d] * Wr[d * E_ + wrp];
    #pragma unroll
    for (int o = 16; o > 0; o >>= 1) p += __shfl_down_sync(0xffffffffu, p, o);
    __shared__ float lg[E_];
    if (lane == 0) lg[wrp] = p + br[wrp];
    __syncthreads();
    if (tid == 0) {
        int i0 = 0; float v0 = lg[0];
        for (int e = 1; e < E_; e++) if (lg[e] > v0) { v0 = lg[e]; i0 = e; }
        int i1 = -1; float v1 = -1e30f;
        for (int e = 0; e < E_; e++) if (e != i0 && lg[e] > v1) { v1 = lg[e]; i1 = e; }
        float e1 = expf(v1 - v0);
        g_topi[n*2] = i0;  g_topi[n*2+1] = i1;
        g_gate[n*2] = 1.f / (1.f + e1);  g_gate[n*2+1] = e1 / (1.f + e1);
        atomicAdd(&g_counts[i0], 1);
        atomicAdd(&g_counts[i1], 1);
    }
}

__global__ void scan_kernel() {
    if (threadIdx.x == 0 && blockIdx.x == 0) {
        int po = 0;
        for (int e = 0; e < E_; e++) {
            g_offsets[e] = po;
            g_cursor[e] = 0;
            int nt = (g_counts[e] + 127) >> 7;
            for (int t = 0; t < nt; t++) g_tile_expert[(po >> 7) + t] = e;
            po += nt << 7;
        }
        for (int t = po >> 7; t < PT; t++) g_tile_expert[t] = -1;
    }
}

__global__ void scatter_kernel() {
    int n = blockIdx.x * blockDim.x + threadIdx.x;
    if (n >= NTOK) return;
    #pragma unroll
    for (int k = 0; k < 2; k++) {
        int e = g_topi[n*2 + k];
        int pos = atomicAdd(&g_cursor[e], 1);
        int s = g_offsets[e] + pos;
        g_slot_token[s] = n;
        g_slot_gate[s]  = g_gate[n*2 + k];
    }
}

// ----------------------------- host ------------------------------------------
template<int CVTA>
static inline void tgemm(const float* A, const float* B, float* C, int M, int N, int K) {
    dim3 grid((M + BM - 1) / BM, N / GBN, 1);
    tgemm_kernel<CVTA><<<grid, 256, SMEM_TG>>>(A, B, C, M, N, K, 0, 0, 0, 1);
}
template<int CVTA>
static inline void tgemm_sk(const float* A, const float* B, float* C, int M, int N, int K, int KS) {
    cudaMemsetAsync(C, 0, (size_t)M * N * sizeof(float), 0);
    dim3 grid((M + BM - 1) / BM, N / GBN, KS);
    tgemm_kernel<CVTA><<<grid, 256, SMEM_TG>>>(A, B, C, M, N, K, 0, 0, 0, KS);
}

extern "C" void kernel_launch(void* const* d_in, const int* in_sizes, int n_in,
                              void* d_out, int out_size) {
    const float* x        = (const float*)d_in[0];
    const float* cosb     = (const float*)d_in[1];
    const float* sinb     = (const float*)d_in[2];
    const float* ln1g     = (const float*)d_in[3];
    const float* ln1b     = (const float*)d_in[4];
    const float* ln2g     = (const float*)d_in[5];
    const float* ln2b     = (const float*)d_in[6];
    const float* ln3g     = (const float*)d_in[7];
    const float* ln3b     = (const float*)d_in[8];
    const float* Lat      = (const float*)d_in[9];
    const float* wq_lat   = (const float*)d_in[10];
    const float* wk_in    = (const float*)d_in[11];
    const float* wv_in    = (const float*)d_in[12];
    const float* wq_in    = (const float*)d_in[13];
    const float* wk_lat   = (const float*)d_in[14];
    const float* wv_lat   = (const float*)d_in[15];
    const float* w_out    = (const float*)d_in[16];
    const float* router_w = (const float*)d_in[17];
    const float* router_b = (const float*)d_in[18];
    const float* We_w     = (const float*)d_in[19];
    const float* We_v     = (const float*)d_in[20];
    const float* We_o     = (const float*)d_in[21];
    const float* lin_w    = (const float*)d_in[22];
    const float* lin_b    = (const float*)d_in[23];
    float* out = (float*)d_out;

    static bool attrDone = false;
    if (!attrDone) {
        cudaFuncSetAttribute(tgemm_kernel<0>, cudaFuncAttributeMaxDynamicSharedMemorySize, SMEM_TG);
        cudaFuncSetAttribute(tgemm_kernel<1>, cudaFuncAttributeMaxDynamicSharedMemorySize, SMEM_TG);
        cudaFuncSetAttribute(moe_g1_kernel, cudaFuncAttributeMaxDynamicSharedMemorySize, SMEM_F);
        cudaFuncSetAttribute(attn_tile_kernel, cudaFuncAttributeMaxDynamicSharedMemorySize, ATTN_SMEM);
        attrDone = true;
    }

    float *pLq, *pK, *pV, *pQx, *pz, *pQl, *pKl, *pVl, *pz2, *pKz, *pVz;
    float *pxl, *pattn, *px1, *pmoe, *px2, *plin, *ph, *pxr;
    int *pcounts;
    cudaGetSymbolAddress((void**)&pLq,  g_Lq);
    cudaGetSymbolAddress((void**)&pK,   g_K);
    cudaGetSymbolAddress((void**)&pV,   g_V);
    cudaGetSymbolAddress((void**)&pQx,  g_Qx);
    cudaGetSymbolAddress((void**)&pz,   g_z);
    cudaGetSymbolAddress((void**)&pQl,  g_Ql);
    cudaGetSymbolAddress((void**)&pKl,  g_Kl);
    cudaGetSymbolAddress((void**)&pVl,  g_Vl);
    cudaGetSymbolAddress((void**)&pz2,  g_z2);
    cudaGetSymbolAddress((void**)&pKz,  g_Kz);
    cudaGetSymbolAddress((void**)&pVz,  g_Vz);
    cudaGetSymbolAddress((void**)&pxl,  g_xl);
    cudaGetSymbolAddress((void**)&pattn,g_attnout);
    cudaGetSymbolAddress((void**)&px1,  g_x1);
    cudaGetSymbolAddress((void**)&pmoe, g_moe);
    cudaGetSymbolAddress((void**)&px2,  g_x2);
    cudaGetSymbolAddress((void**)&plin, g_lin);
    cudaGetSymbolAddress((void**)&ph,   g_h);
    cudaGetSymbolAddress((void**)&pxr,  g_xr);
    cudaGetSymbolAddress((void**)&pcounts, g_counts);

    // ---- attention pipeline ----
    round_kernel<<<(NTOK*D_/4 + 255)/256, 256>>>((const float4*)x, (float4*)pxr, NTOK*D_/4);
    tgemm_sk<1>(Lat, wq_lat, pLq, NL_, DL_, DL_, 8);
    tgemm<0>(pxr, wk_in, pK,  NTOK, DL_, D_);
    tgemm<0>(pxr, wv_in, pV,  NTOK, DL_, D_);
    tgemm<0>(pxr, wq_in, pQx, NTOK, DL_, D_);

    int nrope = NTOK * H_ * HALF_;
    rope_kernel<<<(nrope + 255) / 256, 256>>>(pK,  cosb, sinb);
    rope_kernel<<<(nrope + 255) / 256, 256>>>(pQx, cosb, sinb);

    attn_tile_kernel<<<dim3(1, H_, B_), 256, ATTN_SMEM>>>(pLq, 0, pK, pV, T_, pz, NL_, 1);
    tgemm_sk<1>(pz, wq_lat, pQl, B_*NL_, DL_, DL_, 8);
    tgemm_sk<1>(pz, wk_lat, pKl, B_*NL_, DL_, DL_, 8);
    tgemm_sk<1>(pz, wv_lat, pVl, B_*NL_, DL_, DL_, 8);
    attn_tile_kernel<<<dim3(1, H_, B_), 256, ATTN_SMEM>>>(pQl, NL_, pKl, pVl, NL_, pz2, NL_, 0);
    tgemm_sk<1>(pz2, wk_lat, pKz, B_*NL_, DL_, DL_, 8);
    tgemm_sk<1>(pz2, wv_lat, pVz, B_*NL_, DL_, DL_, 8);
    attn_tile_kernel<<<dim3(T_/64, H_, B_), 256, ATTN_SMEM>>>(pQx, T_, pKz, pVz, NL_, pxl, T_, 0);

    tgemm<0>(pxl, w_out, pattn, NTOK, D_, DL_);
    add_ln_kernel<<<NTOK, 256>>>(x, pattn, ln1g, ln1b, nullptr, px1, pxr);

    // ---- MoE (padded expert tiles) ----
    cudaMemsetAsync(pcounts, 0, E_ * sizeof(int), 0);
    router_kernel<<<NTOK, 256>>>(px1, router_w, router_b);
    scan_kernel<<<1, 32>>>();
    scatter_kernel<<<(NTOK + 255) / 256, 256>>>();

    moe_g1_kernel<<<dim3(PT, DH_/FBN), 512, SMEM_F>>>(pxr, We_w, We_v);

    cudaMemsetAsync(pmoe, 0, (size_t)NTOK * D_ * sizeof(float), 0);
    tgemm_kernel<0><<<dim3(PT, D_/GBN), 256, SMEM_TG>>>(ph, We_o, pmoe, 0, D_, DH_, 1, 0, 1, 1);
    add_ln_kernel<<<NTOK, 256>>>(px1, pmoe, ln2g, ln2b, nullptr, px2, pxr);

    // ---- final linear ----
    tgemm<0>(pxr, lin_w, plin, NTOK, D_, D_);
    add_ln_kernel<<<NTOK, 256>>>(px2, plin, ln3g, ln3b, lin_b, out, nullptr);
}

// round 16
// speedup vs baseline: 1.0769x; 1.0769x over previous
#include <cuda_runtime.h>
#include <cstdint>
#include <math.h>

#define D_    1024
#define DL_   1024
#define DH_   2048
#define NL_   64
#define H_    16
#define E_    8
#define B_    2
#define T_    2048
#define NTOK  (B_*T_)
#define HALF_ 32
#define SLOTS (NTOK*2)
#define SLOTP (SLOTS + E_*128)   /* padded slots: 9216 */
#define PT    (SLOTP/128)        /* 72 tiles */

__device__ float g_Lq[NL_*DL_];
__device__ float g_K [NTOK*DL_];
__device__ float g_V [NTOK*DL_];
__device__ float g_Qx[NTOK*DL_];
__device__ float g_z [B_*NL_*DL_];
__device__ float g_Ql[B_*NL_*DL_];
__device__ float g_Kl[B_*NL_*DL_];
__device__ float g_Vl[B_*NL_*DL_];
__device__ float g_z2[B_*NL_*DL_];
__device__ float g_Kz[B_*NL_*DL_];
__device__ float g_Vz[B_*NL_*DL_];
__device__ float g_xl[NTOK*DL_];
__device__ float g_attnout[NTOK*D_];
__device__ float g_x1[NTOK*D_];
__device__ float g_moe[NTOK*D_];
__device__ float g_x2[NTOK*D_];
__device__ float g_lin[NTOK*D_];
__device__ float g_h [(size_t)SLOTP*DH_];
__device__ float g_xr[NTOK*D_];
__device__ int   g_counts[E_];
__device__ int   g_offsets[E_];
__device__ int   g_cursor[E_];
__device__ int   g_tile_expert[PT];
__device__ int   g_slot_token[SLOTP];
__device__ float g_slot_gate[SLOTP];
__device__ int   g_topi[NTOK*2];
__device__ float g_gate[NTOK*2];

// ----------------------------- tf32 helpers ----------------------------------
__device__ __forceinline__ uint32_t f2tf(float f) {
    uint32_t u; asm("cvt.rna.tf32.f32 %0, %1;" : "=r"(u) : "f"(f)); return u;
}
__device__ __forceinline__ float roundtf(float f) { return __uint_as_float(f2tf(f)); }
__device__ __forceinline__ uint32_t f2tf_bits(uint32_t b) {
    uint32_t u; asm("cvt.rna.tf32.f32 %0, %1;" : "=r"(u) : "f"(__uint_as_float(b))); return u;
}
__device__ __forceinline__ void mma_tf32(float* d, const uint32_t* a, const uint32_t* b) {
    asm volatile("mma.sync.aligned.m16n8k8.row.col.f32.tf32.tf32.f32 "
        "{%0,%1,%2,%3}, {%4,%5,%6,%7}, {%8,%9}, {%0,%1,%2,%3};\n"
        : "+f"(d[0]), "+f"(d[1]), "+f"(d[2]), "+f"(d[3])
        : "r"(a[0]), "r"(a[1]), "r"(a[2]), "r"(a[3]), "r"(b[0]), "r"(b[1]));
}
__device__ __forceinline__ void ldmatrix4(uint32_t* r, uint32_t addr) {
    asm volatile("ldmatrix.sync.aligned.m8n8.x4.shared.b16 {%0,%1,%2,%3}, [%4];"
        : "=r"(r[0]), "=r"(r[1]), "=r"(r[2]), "=r"(r[3]) : "r"(addr));
}
__device__ __forceinline__ void cpasync16(uint32_t dst, const void* src) {
    asm volatile("cp.async.cg.shared.global [%0], [%1], 16;\n" :: "r"(dst), "l"(src));
}
__device__ __forceinline__ void cpcommit() { asm volatile("cp.async.commit_group;\n" ::: "memory"); }
__device__ __forceinline__ void cpwait1()  { asm volatile("cp.async.wait_group 1;\n" ::: "memory"); }
__device__ __forceinline__ void cpwait2()  { asm volatile("cp.async.wait_group 2;\n" ::: "memory"); }

#define ASTR 36

// ----------------------------- rounding prep ----------------------------------
__global__ void round_kernel(const float4* __restrict__ s, float4* __restrict__ d, int n4) {
    int i = blockIdx.x * blockDim.x + threadIdx.x;
    if (i >= n4) return;
    float4 v = s[i];
    v.x = roundtf(v.x); v.y = roundtf(v.y); v.z = roundtf(v.z); v.w = roundtf(v.w);
    d[i] = v;
}

// ----------------------- 2-CTA/SM tf32 GEMM (BM128 x BN128) -------------------
#define BM 128
#define GBN 128
#define BK 32
#define GBSTR 136
#define GAW (BM*ASTR)
#define GBW (BK*GBSTR)
#define GSTG (GAW+GBW)
#define GSTAGES 2
#define SMEM_TG (GSTAGES*GSTG*4)

// expertMode: padded-tile map (grid.x over PT tiles); e = g_tile_expert[x].
template<int CVTA>
__global__ void __launch_bounds__(256, 2) tgemm_kernel(
    const float* __restrict__ A, const float* __restrict__ Bm, float* __restrict__ C,
    int M, int N, int K, int expertMode, int gatherA, int scatterC, int splitK)
{
    extern __shared__ float dsm[];
    __shared__ int   rIn[BM];
    __shared__ int   rOut[BM];
    __shared__ float rGate[BM];

    const int tid = threadIdx.x;
    int kOff = 0, Kloc = K;
    int end;
    if (expertMode) {
        int e = g_tile_expert[blockIdx.x];
        if (e < 0) return;
        Bm += (size_t)e * K * N;
        end = g_offsets[e] + g_counts[e];
    } else {
        if (splitK > 1) { Kloc = K / splitK; kOff = blockIdx.z * Kloc; }
        if (blockIdx.x * BM >= M) return;
        end = M;
    }
    const int tile_m = blockIdx.x * BM;
    const int tile_n = blockIdx.y * GBN;

    if (tid < BM) {
        int m = tile_m + tid;
        if (m < end) {
            rIn[tid]   = gatherA  ? g_slot_token[m] : m;
            rOut[tid]  = scatterC ? g_slot_token[m] : m;
            rGate[tid] = scatterC ? g_slot_gate[m] : 1.f;
        } else { rIn[tid] = 0; rOut[tid] = -1; rGate[tid] = 0.f; }
    }
    __syncthreads();

    const uint32_t smem_u32 = (uint32_t)__cvta_generic_to_shared(dsm);
    const int lane = tid & 31;
    const int wid  = tid >> 5;
    const int wm = (wid >> 2) * 64;
    const int wn = (wid & 3) * 32;
    const int gid = lane >> 2, tig = lane & 3;
    const int lj = lane >> 3, lr = lane & 7;
    const uint32_t aLanePart = ((uint32_t)(wm + (lj & 1) * 8 + lr) * ASTR + (lj >> 1) * 4) * 4u;

    const int a_row = tid >> 3;
    const int a_kc  = (tid & 7) * 4;
    const int b_row = tid >> 5;
    const int b_nc  = (tid & 31) * 4;

    const int nkt = Kloc / BK;

    auto issue = [&](int kt) {
        const int s = kt & 1;
        const int k0 = kOff + kt * BK;
        const uint32_t aBase = smem_u32 + s * (GSTG * 4);
        const uint32_t bBase = aBase + GAW * 4;
        #pragma unroll
        for (int i = 0; i < 4; i++) {
            int row = a_row + i * 32;
            int ar = rIn[row];
            cpasync16(aBase + ((uint32_t)row * ASTR + a_kc) * 4u,
                      A + (size_t)ar * K + k0 + a_kc);
        }
        #pragma unroll
        for (int i = 0; i < 4; i++) {
            int row = b_row + i * 8;
            cpasync16(bBase + ((uint32_t)row * GBSTR + b_nc) * 4u,
                      Bm + (size_t)(k0 + row) * N + tile_n + b_nc);
        }
    };

    float acc[4][4][4];
    #pragma unroll
    for (int i = 0; i < 4; i++)
        #pragma unroll
        for (int j = 0; j < 4; j++)
            #pragma unroll
            for (int q = 0; q < 4; q++) acc[i][j][q] = 0.f;

    issue(0); cpcommit();
    if (nkt > 1) { issue(1); cpcommit(); }

    for (int kt = 0; kt < nkt; kt++) {
        cpwait1();
        __syncthreads();

        const int s = kt & 1;
        const uint32_t aBase = smem_u32 + s * (GSTG * 4) + aLanePart;
        const float* Bs = dsm + s * GSTG + GAW;

        #pragma unroll
        for (int ks = 0; ks < 4; ks++) {
            uint32_t af[4][4];
            #pragma unroll
            for (int mi = 0; mi < 4; mi++) {
                ldmatrix4(af[mi], aBase + mi * (16 * ASTR * 4) + ks * 32);
                if (CVTA) {
                    #pragma unroll
                    for (int q = 0; q < 4; q++) af[mi][q] = f2tf_bits(af[mi][q]);
                }
            }
            uint32_t bf[4][2];
            #pragma unroll
            for (int ni = 0; ni < 4; ni++) {
                int idx = (ks * 8 + tig) * GBSTR + wn + ni * 8 + gid;
                bf[ni][0] = f2tf(Bs[idx]);
                bf[ni][1] = f2tf(Bs[idx + 4 * GBSTR]);
            }
            #pragma unroll
            for (int mi = 0; mi < 4; mi++)
                #pragma unroll
                for (int ni = 0; ni < 4; ni++)
                    mma_tf32(acc[mi][ni], af[mi], bf[ni]);
        }
        __syncthreads();
        if (kt + 2 < nkt) issue(kt + 2);
        cpcommit();
    }

    const bool atom = (scatterC != 0) || (splitK > 1);
    #pragma unroll
    for (int mi = 0; mi < 4; mi++) {
        int rl0 = wm + mi * 16 + gid;
        int rl1 = rl0 + 8;
        int o0 = rOut[rl0], o1 = rOut[rl1];
        float g0 = rGate[rl0], g1 = rGate[rl1];
        #pragma unroll
        for (int ni = 0; ni < 4; ni++) {
            int c = tile_n + wn + ni * 8 + tig * 2;
            if (atom) {
                if (o0 >= 0) {
                    atomicAdd(&C[(size_t)o0 * N + c],     g0 * acc[mi][ni][0]);
                    atomicAdd(&C[(size_t)o0 * N + c + 1], g0 * acc[mi][ni][1]);
                }
                if (o1 >= 0) {
                    atomicAdd(&C[(size_t)o1 * N + c],     g1 * acc[mi][ni][2]);
                    atomicAdd(&C[(size_t)o1 * N + c + 1], g1 * acc[mi][ni][3]);
                }
            } else {
                if (o0 >= 0) *(float2*)&C[(size_t)o0 * N + c] = make_float2(acc[mi][ni][0], acc[mi][ni][1]);
                if (o1 >= 0) *(float2*)&C[(size_t)o1 * N + c] = make_float2(acc[mi][ni][2], acc[mi][ni][3]);
            }
        }
    }
}

// ------- fused MoE gemm1 + SwiGLU (R14 256-thread kernel, padded-tile map) ----
#define FBN 128
#define FBSTR 136
#define FAW (BM*ASTR)
#define FBW (BK*FBSTR)
#define FSTAGE (FAW+2*FBW)
#define FSTAGES 3
#define SMEM_F (FSTAGES*FSTAGE*4)
__global__ void __launch_bounds__(256) moe_g1_kernel(
    const float* __restrict__ A, const float* __restrict__ Ww, const float* __restrict__ Wv)
{
    extern __shared__ float dsm[];
    __shared__ int rIn[BM];
    __shared__ int rOut[BM];

    const int tid = threadIdx.x;
    const int e = g_tile_expert[blockIdx.x];
    if (e < 0) return;
    const int end = g_offsets[e] + g_counts[e];
    const int tile_m = blockIdx.x * BM;
    const int tile_n = blockIdx.y * FBN;
    Ww += (size_t)e * D_ * DH_;
    Wv += (size_t)e * D_ * DH_;

    if (tid < BM) {
        int m = tile_m + tid;
        if (m < end) { rIn[tid] = g_slot_token[m]; rOut[tid] = m; }
        else         { rIn[tid] = 0; rOut[tid] = -1; }
    }
    __syncthreads();

    const uint32_t smem_u32 = (uint32_t)__cvta_generic_to_shared(dsm);
    const int lane = tid & 31;
    const int wid  = tid >> 5;
    const int wm = (wid >> 2) * 64;
    const int wn = (wid & 3) * 32;
    const int gid = lane >> 2, tig = lane & 3;
    const int lj = lane >> 3, lr = lane & 7;
    const uint32_t aLanePart = ((uint32_t)(wm + (lj & 1) * 8 + lr) * ASTR + (lj >> 1) * 4) * 4u;

    const int a_row = tid >> 3;
    const int a_kc  = (tid & 7) * 4;
    const int b_row = tid >> 5;
    const int b_nc  = (tid & 31) * 4;

    const int nkt = D_ / BK;

    auto issue = [&](int kt) {
        const int s = kt % FSTAGES;
        const int k0 = kt * BK;
        const uint32_t aBase = smem_u32 + s * (FSTAGE * 4);
        const uint32_t wBase = aBase + FAW * 4;
        const uint32_t vBase = wBase + FBW * 4;
        #pragma unroll
        for (int i = 0; i < 4; i++) {
            int row = a_row + i * 32;
            int ar = rIn[row];
            cpasync16(aBase + ((uint32_t)row * ASTR + a_kc) * 4u,
                      A + (size_t)ar * D_ + k0 + a_kc);
        }
        #pragma unroll
        for (int i = 0; i < 4; i++) {
            int row = b_row + i * 8;
            cpasync16(wBase + ((uint32_t)row * FBSTR + b_nc) * 4u,
                      Ww + (size_t)(k0 + row) * DH_ + tile_n + b_nc);
            cpasync16(vBase + ((uint32_t)row * FBSTR + b_nc) * 4u,
                      Wv + (size_t)(k0 + row) * DH_ + tile_n + b_nc);
        }
    };

    float accW[4][4][4], accV[4][4][4];
    #pragma unroll
    for (int i = 0; i < 4; i++)
        #pragma unroll
        for (int j = 0; j < 4; j++)
            #pragma unroll
            for (int q = 0; q < 4; q++) { accW[i][j][q] = 0.f; accV[i][j][q] = 0.f; }

    issue(0); cpcommit();
    if (nkt > 1) issue(1); cpcommit();

    for (int kt = 0; kt < nkt; kt++) {
        if (kt + 2 < nkt) issue(kt + 2);
        cpcommit();
        cpwait2();
        __syncthreads();

        const int s = kt % FSTAGES;
        const uint32_t aBase = smem_u32 + s * (FSTAGE * 4) + aLanePart;
        const float* Bw = dsm + s * FSTAGE + FAW;
        const float* Bv = Bw + FBW;

        #pragma unroll
        for (int ks = 0; ks < 4; ks++) {
            uint32_t af[4][4];
            #pragma unroll
            for (int mi = 0; mi < 4; mi++)
                ldmatrix4(af[mi], aBase + mi * (16 * ASTR * 4) + ks * 32);  // A pre-rounded
            uint32_t bw[4][2], bv[4][2];
            #pragma unroll
            for (int ni = 0; ni < 4; ni++) {
                int idx = (ks * 8 + tig) * FBSTR + wn + ni * 8 + gid;
                bw[ni][0] = f2tf(Bw[idx]);
                bw[ni][1] = f2tf(Bw[idx + 4 * FBSTR]);
                bv[ni][0] = f2tf(Bv[idx]);
                bv[ni][1] = f2tf(Bv[idx + 4 * FBSTR]);
            }
            #pragma unroll
            for (int mi = 0; mi < 4; mi++)
                #pragma unroll
                for (int ni = 0; ni < 4; ni++) {
                    mma_tf32(accW[mi][ni], af[mi], bw[ni]);
                    mma_tf32(accV[mi][ni], af[mi], bv[ni]);
                }
        }
        __syncthreads();
    }

    // epilogue: h = round(a * silu(b))
    #pragma unroll
    for (int mi = 0; mi < 4; mi++) {
        int rl0 = wm + mi * 16 + gid;
        int rl1 = rl0 + 8;
        int s0 = rOut[rl0], s1 = rOut[rl1];
        #pragma unroll
        for (int ni = 0; ni < 4; ni++) {
            int c = tile_n + wn + ni * 8 + tig * 2;
            if (s0 >= 0) {
                float b0 = accV[mi][ni][0], b1 = accV[mi][ni][1];
                float h0 = accW[mi][ni][0] * b0 / (1.f + __expf(-b0));
                float h1 = accW[mi][ni][1] * b1 / (1.f + __expf(-b1));
                *(float2*)&g_h[(size_t)s0 * DH_ + c] = make_float2(roundtf(h0), roundtf(h1));
            }
            if (s1 >= 0) {
                float b2 = accV[mi][ni][2], b3 = accV[mi][ni][3];
                float h2 = accW[mi][ni][2] * b2 / (1.f + __expf(-b2));
                float h3 = accW[mi][ni][3] * b3 / (1.f + __expf(-b3));
                *(float2*)&g_h[(size_t)s1 * DH_ + c] = make_float2(roundtf(h2), roundtf(h3));
            }
        }
    }
}

// ----------------------------- tiled attention (verbatim R14) -----------------
#define APAD 68
#define ATTN_SMEM (3*64*APAD*4)
__global__ void __launch_bounds__(256) attn_tile_kernel(
    const float* __restrict__ Q, int qbs,
    const float* __restrict__ Ksrc, const float* __restrict__ Vsrc, int kbs,
    float* __restrict__ Out, int obs, int causal)
{
    extern __shared__ float sm[];
    float* Ks = sm;
    float* Vs = sm + 64 * APAD;
    float* Ws = sm + 2 * 64 * APAD;

    const int tid = threadIdx.x;
    const int h = blockIdx.y, b = blockIdx.z;
    const int qtile = blockIdx.x * 64;

    {
        int row = tid >> 2;
        int c0 = (tid & 3) * 16;
        const float* kp = Ksrc + ((size_t)(b * kbs + row)) * DL_ + h * 64 + c0;
        const float* vp = Vsrc + ((size_t)(b * kbs + row)) * DL_ + h * 64 + c0;
        const float* qp = Q    + ((size_t)(b * qbs + qtile + row)) * DL_ + h * 64 + c0;
        #pragma unroll
        for (int j = 0; j < 4; j++) {
            *(float4*)&Ks[row * APAD + c0 + 4*j] = __ldg((const float4*)kp + j);
            *(float4*)&Vs[row * APAD + c0 + 4*j] = __ldg((const float4*)vp + j);
            *(float4*)&Ws[row * APAD + c0 + 4*j] = __ldg((const float4*)qp + j);
        }
    }
    __syncthreads();

    const int ty = tid >> 4, tx = tid & 15;
    const int q0 = ty * 4, j0 = tx * 4;

    float acc[4][4] = {};
    #pragma unroll
    for (int d4 = 0; d4 < 16; d4++) {
        float4 k4[4];
        #pragma unroll
        for (int kk = 0; kk < 4; kk++) k4[kk] = *(float4*)&Ks[(j0 + kk) * APAD + d4 * 4];
        #pragma unroll
        for (int i = 0; i < 4; i++) {
            float4 q4 = *(float4*)&Ws[(q0 + i) * APAD + d4 * 4];
            #pragma unroll
            for (int kk = 0; kk < 4; kk++)
                acc[i][kk] += q4.x * k4[kk].x + q4.y * k4[kk].y + q4.z * k4[kk].z + q4.w * k4[kk].w;
        }
    }
    #pragma unroll
    for (int i = 0; i < 4; i++)
        #pragma unroll
        for (int kk = 0; kk < 4; kk++) {
            float s = acc[i][kk] * 0.125f;
            if (causal && (j0 + kk > qtile + q0 + i)) s = -1e30f;
            acc[i][kk] = s;
        }
    __syncthreads();

    #pragma unroll
    for (int i = 0; i < 4; i++) {
        float m = fmaxf(fmaxf(acc[i][0], acc[i][1]), fmaxf(acc[i][2], acc[i][3]));
        #pragma unroll
        for (int off = 1; off < 16; off <<= 1) m = fmaxf(m, __shfl_xor_sync(0xffffffffu, m, off));
        float e[4], sum = 0.f;
        #pragma unroll
        for (int kk = 0; kk < 4; kk++) { e[kk] = __expf(acc[i][kk] - m); sum += e[kk]; }
        #pragma unroll
        for (int off = 1; off < 16; off <<= 1) sum += __shfl_xor_sync(0xffffffffu, sum, off);
        float inv = 1.f / sum;
        #pragma unroll
        for (int kk = 0; kk < 4; kk++) Ws[(q0 + i) * APAD + j0 + kk] = e[kk] * inv;
    }
    __syncthreads();

    float o[4][4] = {};
    const int d0 = tx * 4;
    for (int j = 0; j < 64; j++) {
        float4 v4 = *(float4*)&Vs[j * APAD + d0];
        #pragma unroll
        for (int i = 0; i < 4; i++) {
            float w = Ws[(q0 + i) * APAD + j];
            o[i][0] += w * v4.x; o[i][1] += w * v4.y;
            o[i][2] += w * v4.z; o[i][3] += w * v4.w;
        }
    }
    #pragma unroll
    for (int i = 0; i < 4; i++) {
        float4 r = make_float4(roundtf(o[i][0]), roundtf(o[i][1]),
                               roundtf(o[i][2]), roundtf(o[i][3]));
        *(float4*)&Out[((size_t)(b * obs + qtile + q0 + i)) * DL_ + h * 64 + d0] = r;
    }
}

// ----------------------------- RoPE ------------------------------------------
__global__ void rope_kernel(float* __restrict__ buf, const float* __restrict__ cosb,
                            const float* __restrict__ sinb) {
    int idx = blockIdx.x * blockDim.x + threadIdx.x;
    if (idx >= NTOK * H_ * HALF_) return;
    int j = idx & 31;
    int h = (idx >> 5) & 15;
    int r = idx >> 9;
    int t = r % T_;
    float c = cosb[t * HALF_ + j];
    float s = sinb[t * HALF_ + j];
    size_t base = (size_t)r * DL_ + h * 64 + 2 * j;
    float x1 = buf[base], x2 = buf[base + 1];
    buf[base]     = x1 * c - x2 * s;
    buf[base + 1] = x1 * s + x2 * c;
}

// ----------------------------- LayerNorm(+residual+bias), dual output --------
__global__ void add_ln_kernel(const float* __restrict__ src, const float* __restrict__ addv,
                              const float* __restrict__ g, const float* __restrict__ bt,
                              const float* __restrict__ bias, float* __restrict__ out,
                              float* __restrict__ out_r) {
    int row = blockIdx.x;
    int tid = threadIdx.x;
    const float* x = src + (size_t)row * D_;
    float v[4];
    #pragma unroll
    for (int i = 0; i < 4; i++) v[i] = x[tid + i * 256];
    __shared__ float red[256];
    float s = v[0] + v[1] + v[2] + v[3];
    red[tid] = s; __syncthreads();
    for (int o = 128; o > 0; o >>= 1) { if (tid < o) red[tid] += red[tid + o]; __syncthreads(); }
    float mean = red[0] * (1.f / 1024.f);
    __syncthreads();
    float d0 = v[0]-mean, d1 = v[1]-mean, d2 = v[2]-mean, d3 = v[3]-mean;
    red[tid] = d0*d0 + d1*d1 + d2*d2 + d3*d3; __syncthreads();
    for (int o = 128; o > 0; o >>= 1) { if (tid < o) red[tid] += red[tid + o]; __syncthreads(); }
    float stdv = sqrtf(red[0] * (1.f / 1023.f));
    float inv = 1.f / (stdv + 1e-6f);
    #pragma unroll
    for (int i = 0; i < 4; i++) {
        int c = tid + i * 256;
        float r = g[c] * (v[i] - mean) * inv + bt[c] + addv[(size_t)row * D_ + c];
        if (bias) r += bias[c];
        out[(size_t)row * D_ + c] = r;
        if (out_r) out_r[(size_t)row * D_ + c] = roundtf(r);
    }
}

// ----------------------------- router + routing ------------------------------
__global__ void router_kernel(const float* __restrict__ X, const float* __restrict__ Wr,
                              const float* __restrict__ br) {
    int n = blockIdx.x;
    int tid = threadIdx.x;
    int wrp = tid >> 5, lane = tid & 31;
    const float* xr = X + (size_t)n * D_;
    float p = 0.f;
    for (int d = lane; d < D_; d += 32) p += xr[d] * Wr[d * E_ + wrp];
    #pragma unroll
    for (int o = 16; o > 0; o >>= 1) p += __shfl_down_sync(0xffffffffu, p, o);
    __shared__ float lg[E_];
    if (lane == 0) lg[wrp] = p + br[wrp];
    __syncthreads();
    if (tid == 0) {
        int i0 = 0; float v0 = lg[0];
        for (int e = 1; e < E_; e++) if (lg[e] > v0) { v0 = lg[e]; i0 = e; }
        int i1 = -1; float v1 = -1e30f;
        for (int e = 0; e < E_; e++) if (e != i0 && lg[e] > v1) { v1 = lg[e]; i1 = e; }
        float e1 = expf(v1 - v0);
        g_topi[n*2] = i0;  g_topi[n*2+1] = i1;
        g_gate[n*2] = 1.f / (1.f + e1);  g_gate[n*2+1] = e1 / (1.f + e1);
        atomicAdd(&g_counts[i0], 1);
        atomicAdd(&g_counts[i1], 1);
    }
}

__global__ void scan_kernel() {
    if (threadIdx.x == 0 && blockIdx.x == 0) {
        int po = 0;
        for (int e = 0; e < E_; e++) {
            g_offsets[e] = po;
            g_cursor[e] = 0;
            int nt = (g_counts[e] + 127) >> 7;
            for (int t = 0; t < nt; t++) g_tile_expert[(po >> 7) + t] = e;
            po += nt << 7;
        }
        for (int t = po >> 7; t < PT; t++) g_tile_expert[t] = -1;
    }
}

__global__ void scatter_kernel() {
    int n = blockIdx.x * blockDim.x + threadIdx.x;
    if (n >= NTOK) return;
    #pragma unroll
    for (int k = 0; k < 2; k++) {
        int e = g_topi[n*2 + k];
        int pos = atomicAdd(&g_cursor[e], 1);
        int s = g_offsets[e] + pos;
        g_slot_token[s] = n;
        g_slot_gate[s]  = g_gate[n*2 + k];
    }
}

// ----------------------------- host ------------------------------------------
template<int CVTA>
static inline void tgemm(const float* A, const float* B, float* C, int M, int N, int K) {
    dim3 grid((M + BM - 1) / BM, N / GBN, 1);
    tgemm_kernel<CVTA><<<grid, 256, SMEM_TG>>>(A, B, C, M, N, K, 0, 0, 0, 1);
}
template<int CVTA>
static inline void tgemm_sk(const float* A, const float* B, float* C, int M, int N, int K, int KS) {
    cudaMemsetAsync(C, 0, (size_t)M * N * sizeof(float), 0);
    dim3 grid((M + BM - 1) / BM, N / GBN, KS);
    tgemm_kernel<CVTA><<<grid, 256, SMEM_TG>>>(A, B, C, M, N, K, 0, 0, 0, KS);
}

extern "C" void kernel_launch(void* const* d_in, const int* in_sizes, int n_in,
                              void* d_out, int out_size) {
    const float* x        = (const float*)d_in[0];
    const float* cosb     = (const float*)d_in[1];
    const float* sinb     = (const float*)d_in[2];
    const float* ln1g     = (const float*)d_in[3];
    const float* ln1b     = (const float*)d_in[4];
    const float* ln2g     = (const float*)d_in[5];
    const float* ln2b     = (const float*)d_in[6];
    const float* ln3g     = (const float*)d_in[7];
    const float* ln3b     = (const float*)d_in[8];
    const float* Lat      = (const float*)d_in[9];
    const float* wq_lat   = (const float*)d_in[10];
    const float* wk_in    = (const float*)d_in[11];
    const float* wv_in    = (const float*)d_in[12];
    const float* wq_in    = (const float*)d_in[13];
    const float* wk_lat   = (const float*)d_in[14];
    const float* wv_lat   = (const float*)d_in[15];
    const float* w_out    = (const float*)d_in[16];
    const float* router_w = (const float*)d_in[17];
    const float* router_b = (const float*)d_in[18];
    const float* We_w     = (const float*)d_in[19];
    const float* We_v     = (const float*)d_in[20];
    const float* We_o     = (const float*)d_in[21];
    const float* lin_w    = (const float*)d_in[22];
    const float* lin_b    = (const float*)d_in[23];
    float* out = (float*)d_out;

    static bool attrDone = false;
    if (!attrDone) {
        cudaFuncSetAttribute(tgemm_kernel<0>, cudaFuncAttributeMaxDynamicSharedMemorySize, SMEM_TG);
        cudaFuncSetAttribute(tgemm_kernel<1>, cudaFuncAttributeMaxDynamicSharedMemorySize, SMEM_TG);
        cudaFuncSetAttribute(moe_g1_kernel, cudaFuncAttributeMaxDynamicSharedMemorySize, SMEM_F);
        cudaFuncSetAttribute(attn_tile_kernel, cudaFuncAttributeMaxDynamicSharedMemorySize, ATTN_SMEM);
        attrDone = true;
    }

    float *pLq, *pK, *pV, *pQx, *pz, *pQl, *pKl, *pVl, *pz2, *pKz, *pVz;
    float *pxl, *pattn, *px1, *pmoe, *px2, *plin, *ph, *pxr;
    int *pcounts;
    cudaGetSymbolAddress((void**)&pLq,  g_Lq);
    cudaGetSymbolAddress((void**)&pK,   g_K);
    cudaGetSymbolAddress((void**)&pV,   g_V);
    cudaGetSymbolAddress((void**)&pQx,  g_Qx);
    cudaGetSymbolAddress((void**)&pz,   g_z);
    cudaGetSymbolAddress((void**)&pQl,  g_Ql);
    cudaGetSymbolAddress((void**)&pKl,  g_Kl);
    cudaGetSymbolAddress((void**)&pVl,  g_Vl);
    cudaGetSymbolAddress((void**)&pz2,  g_z2);
    cudaGetSymbolAddress((void**)&pKz,  g_Kz);
    cudaGetSymbolAddress((void**)&pVz,  g_Vz);
    cudaGetSymbolAddress((void**)&pxl,  g_xl);
    cudaGetSymbolAddress((void**)&pattn,g_attnout);
    cudaGetSymbolAddress((void**)&px1,  g_x1);
    cudaGetSymbolAddress((void**)&pmoe, g_moe);
    cudaGetSymbolAddress((void**)&px2,  g_x2);
    cudaGetSymbolAddress((void**)&plin, g_lin);
    cudaGetSymbolAddress((void**)&ph,   g_h);
    cudaGetSymbolAddress((void**)&pxr,  g_xr);
    cudaGetSymbolAddress((void**)&pcounts, g_counts);

    // ---- attention pipeline ----
    round_kernel<<<(NTOK*D_/4 + 255)/256, 256>>>((const float4*)x, (float4*)pxr, NTOK*D_/4);
    tgemm_sk<1>(Lat, wq_lat, pLq, NL_, DL_, DL_, 8);
    tgemm<0>(pxr, wk_in, pK,  NTOK, DL_, D_);
    tgemm<0>(pxr, wv_in, pV,  NTOK, DL_, D_);
    tgemm<0>(pxr, wq_in, pQx, NTOK, DL_, D_);

    int nrope = NTOK * H_ * HALF_;
    rope_kernel<<<(nrope + 255) / 256, 256>>>(pK,  cosb, sinb);
    rope_kernel<<<(nrope + 255) / 256, 256>>>(pQx, cosb, sinb);

    attn_tile_kernel<<<dim3(1, H_, B_), 256, ATTN_SMEM>>>(pLq, 0, pK, pV, T_, pz, NL_, 1);
    tgemm_sk<1>(pz, wq_lat, pQl, B_*NL_, DL_, DL_, 8);
    tgemm_sk<1>(pz, wk_lat, pKl, B_*NL_, DL_, DL_, 8);
    tgemm_sk<1>(pz, wv_lat, pVl, B_*NL_, DL_, DL_, 8);
    attn_tile_kernel<<<dim3(1, H_, B_), 256, ATTN_SMEM>>>(pQl, NL_, pKl, pVl, NL_, pz2, NL_, 0);
    tgemm_sk<1>(pz2, wk_lat, pKz, B_*NL_, DL_, DL_, 8);
    tgemm_sk<1>(pz2, wv_lat, pVz, B_*NL_, DL_, DL_, 8);
    attn_tile_kernel<<<dim3(T_/64, H_, B_), 256, ATTN_SMEM>>>(pQx, T_, pKz, pVz, NL_, pxl, T_, 0);

    tgemm<0>(pxl, w_out, pattn, NTOK, D_, DL_);
    add_ln_kernel<<<NTOK, 256>>>(x, pattn, ln1g, ln1b, nullptr, px1, pxr);

    // ---- MoE (padded expert tiles) ----
    cudaMemsetAsync(pcounts, 0, E_ * sizeof(int), 0);
    router_kernel<<<NTOK, 256>>>(px1, router_w, router_b);
    scan_kernel<<<1, 32>>>();
    scatter_kernel<<<(NTOK + 255) / 256, 256>>>();

    moe_g1_kernel<<<dim3(PT, DH_/FBN), 256, SMEM_F>>>(pxr, We_w, We_v);

    cudaMemsetAsync(pmoe, 0, (size_t)NTOK * D_ * sizeof(float), 0);
    tgemm_kernel<0><<<dim3(PT, D_/GBN), 256, SMEM_TG>>>(ph, We_o, pmoe, 0, D_, DH_, 1, 0, 1, 1);
    add_ln_kernel<<<NTOK, 256>>>(px1, pmoe, ln2g, ln2b, nullptr, px2, pxr);

    // ---- final linear ----
    tgemm<0>(pxr, lin_w, plin, NTOK, D_, D_);
    add_ln_kernel<<<NTOK, 256>>>(px2, plin, ln3g, ln3b, lin_b, out, nullptr);
}